// round 16
// baseline (speedup 1.0000x reference)
#include <cuda_runtime.h>
#include <cuda_bf16.h>
#include <cstdint>

// Problem constants
#define Bn 32
#define Ln 256
#define Dn 256
#define Hn 256
#define En 8
#define NLn 4
#define Kc 4
#define MROWS (Bn*En*Ln)     // 65536

#define SSTRIDE 264          // bf16 elems per smem row (pad: stride%32banks=4)

__device__ __forceinline__ float fast_tanh(float x)
{
    float y;
    asm("tanh.approx.f32 %0, %1;" : "=f"(y) : "f"(x));
    return y;
}

__device__ __forceinline__ uint32_t s2u(const void* p)
{
    uint32_t a;
    asm("{ .reg .u64 t; cvta.to.shared.u64 t, %1; cvt.u32.u64 %0, t; }"
        : "=r"(a) : "l"(p));
    return a;
}

// pack two fp32 -> bf16x2 (lo in low half)
__device__ __forceinline__ unsigned int pbf2(float lo, float hi)
{
    unsigned int r;
    asm("cvt.rn.bf16x2.f32 %0, %1, %2;" : "=r"(r) : "f"(hi), "f"(lo));
    return r;
}

#define MMA_BF16(c, a, b) \
    asm volatile( \
        "mma.sync.aligned.m16n8k16.row.col.f32.bf16.bf16.f32 " \
        "{%0,%1,%2,%3}, {%4,%5,%6,%7}, {%8,%9}, {%0,%1,%2,%3};" \
        : "+f"((c)[0]), "+f"((c)[1]), "+f"((c)[2]), "+f"((c)[3]) \
        : "r"((a)[0]), "r"((a)[1]), "r"((a)[2]), "r"((a)[3]), \
          "r"((b)[0]), "r"((b)[1]))

// Scratch (device globals - no allocation allowed)
__device__ float g_ln[Bn*Ln*Dn];                              // 8 MB
__device__ float g_pre[(size_t)Bn*En*Ln*Hn];                  // 64 MB
__device__ __nv_bfloat16 g_uhi[Bn*Ln*Dn];                     // 4 MB
__device__ __nv_bfloat16 g_ulo[Bn*Ln*Dn];                     // 4 MB
__device__ __nv_bfloat16 g_yhi[(size_t)Bn*En*Ln*Hn];          // 32 MB
__device__ __nv_bfloat16 g_ylo[(size_t)Bn*En*Ln*Hn];          // 32 MB
__device__ __nv_bfloat16 g_whi[En*Hn*Dn];                     // 1 MB (per layer)
__device__ __nv_bfloat16 g_wlo[En*Hn*Dn];                     // 1 MB

// ---------------------------------------------------------------------------
// LayerNorm
// ---------------------------------------------------------------------------
__global__ void ln_kernel(const float* __restrict__ x, const float* __restrict__ g,
                          const float* __restrict__ bb, float* __restrict__ out)
{
    int token = blockIdx.x;
    int t = threadIdx.x;
    __shared__ float red[8];
    __shared__ float meanv, rstdv;

    float v = x[(size_t)token * Dn + t];

    float s = v;
    #pragma unroll
    for (int o = 16; o > 0; o >>= 1) s += __shfl_xor_sync(0xffffffffu, s, o);
    if ((t & 31) == 0) red[t >> 5] = s;
    __syncthreads();
    if (t == 0) {
        float m = 0.f;
        #pragma unroll
        for (int i = 0; i < 8; i++) m += red[i];
        meanv = m * (1.0f / Dn);
    }
    __syncthreads();

    float d = v - meanv;
    float sq = d * d;
    #pragma unroll
    for (int o = 16; o > 0; o >>= 1) sq += __shfl_xor_sync(0xffffffffu, sq, o);
    if ((t & 31) == 0) red[t >> 5] = sq;
    __syncthreads();
    if (t == 0) {
        float vv = 0.f;
        #pragma unroll
        for (int i = 0; i < 8; i++) vv += red[i];
        rstdv = rsqrtf(vv * (1.0f / Dn) + 1e-5f);
    }
    __syncthreads();

    out[(size_t)token * Dn + t] = d * rstdv * g[t] + bb[t];
}

// ---------------------------------------------------------------------------
// Depthwise causal conv1d (K=4, left pad 3) + bias -> split-bf16 output
// ---------------------------------------------------------------------------
__global__ void conv_kernel(const float* __restrict__ ln, const float* __restrict__ cw,
                            const float* __restrict__ cb,
                            __nv_bfloat16* __restrict__ uhi,
                            __nv_bfloat16* __restrict__ ulo)
{
    int idx = blockIdx.x * 256 + threadIdx.x;
    int d  = idx & 255;
    int l  = (idx >> 8) & 255;
    int b0 = idx >> 16;
    float acc = cb[d];
    #pragma unroll
    for (int j = 0; j < Kc; j++) {
        int ls = l - (Kc - 1) + j;
        if (ls >= 0)
            acc += ln[((size_t)b0 * Ln + ls) * Dn + d] * cw[d * Kc + j];
    }
    __nv_bfloat16 h = __float2bfloat16(acc);
    uhi[idx] = h;
    ulo[idx] = __float2bfloat16(acc - __bfloat162float(h));
}

// ---------------------------------------------------------------------------
// wprep: fold r into W_ih per-ensemble, split to bf16 hi/lo.
// Wr[e][h][f] = Wih[h][f] * r[e][f]
// ---------------------------------------------------------------------------
__global__ void wprep_kernel(const float* __restrict__ Wih, const float* __restrict__ rv,
                             __nv_bfloat16* __restrict__ whi,
                             __nv_bfloat16* __restrict__ wlo)
{
    int idx = blockIdx.x * 256 + threadIdx.x;    // En*Hn*Dn = 524288
    int f = idx & 255;
    int h = (idx >> 8) & 255;
    int e = idx >> 16;
    float w = Wih[h * 256 + f] * rv[e * 256 + f];
    __nv_bfloat16 hi = __float2bfloat16(w);
    whi[idx] = hi;
    wlo[idx] = __float2bfloat16(w - __bfloat162float(hi));
}

// ---------------------------------------------------------------------------
// gemm4: mma.sync bf16 split GEMM with pre-split inputs (pure copies into
// smem; mma core + layout identical to the proven gemm3).
// A = y (or u for layer0) hi/lo, B = Wr[e] hi/lo (r pre-folded).
// ---------------------------------------------------------------------------
#define OFF_AHI 0
#define OFF_ALO (128*SSTRIDE)
#define OFF_BHI (256*SSTRIDE)
#define OFF_BLO (320*SSTRIDE)
#define SM3_ELEMS (384*SSTRIDE)
#define SM3_BYTES (SM3_ELEMS*2)

__global__ __launch_bounds__(256, 1)
void gemm4_kernel(const __nv_bfloat16* __restrict__ inhi,
                  const __nv_bfloat16* __restrict__ inlo,
                  const __nv_bfloat16* __restrict__ whi,
                  const __nv_bfloat16* __restrict__ wlo,
                  const float* __restrict__ sv,
                  const float* __restrict__ bv, float* __restrict__ pre, int layer0)
{
    extern __shared__ __align__(16) __nv_bfloat16 sm[];
    int tid = threadIdx.x;
    int wid = tid >> 5;
    int lane = tid & 31;
    int bm = blockIdx.x;                 // 512 M-tiles of 128 rows

    int eT = (bm >> 1) & 7;              // ensemble index for this tile

    // ---- Copy A tile hi/lo: 128 rows x 256 k (once) -------------------------
    {
        int row = tid >> 1;
        int kh  = (tid & 1) * 128;
        int rowA = bm * 128 + row;
        size_t srcRow = layer0 ? ((size_t)(rowA >> 11) * 256 + (rowA & 255))
                               : (size_t)rowA;
        const __nv_bfloat16* ah = inhi + srcRow * 256 + kh;
        const __nv_bfloat16* al = inlo + srcRow * 256 + kh;
        __nv_bfloat16* dh = sm + OFF_AHI + row * SSTRIDE + kh;
        __nv_bfloat16* dl = sm + OFF_ALO + row * SSTRIDE + kh;
        #pragma unroll
        for (int g = 0; g < 16; g++) {
            *(uint4*)(dh + g * 8) = *(const uint4*)(ah + g * 8);
            *(uint4*)(dl + g * 8) = *(const uint4*)(al + g * 8);
        }
    }

    int warp_m = wid & 3;
    int warp_n = wid >> 2;
    int grp = lane >> 2;
    int tg  = lane & 3;

    const __nv_bfloat16* wbh = whi + (size_t)eT * 256 * 256;
    const __nv_bfloat16* wbl = wlo + (size_t)eT * 256 * 256;

    for (int bn = 0; bn < 4; bn++) {
        __syncthreads();   // A ready (bn=0) / previous mma reads done
        // ---- Copy B tile hi/lo: 64 rows(h) x 256 k ---------------------------
        {
            int row = tid >> 2;
            int kq  = (tid & 3) * 64;
            const __nv_bfloat16* bh = wbh + (size_t)(bn * 64 + row) * 256 + kq;
            const __nv_bfloat16* bl = wbl + (size_t)(bn * 64 + row) * 256 + kq;
            __nv_bfloat16* dh = sm + OFF_BHI + row * SSTRIDE + kq;
            __nv_bfloat16* dl = sm + OFF_BLO + row * SSTRIDE + kq;
            #pragma unroll
            for (int g = 0; g < 8; g++) {
                *(uint4*)(dh + g * 8) = *(const uint4*)(bh + g * 8);
                *(uint4*)(dl + g * 8) = *(const uint4*)(bl + g * 8);
            }
        }
        __syncthreads();

        // ---- Warp mma loop (identical to gemm3) ------------------------------
        float acc[2][4][4];
        #pragma unroll
        for (int mt = 0; mt < 2; mt++)
            #pragma unroll
            for (int n8 = 0; n8 < 4; n8++)
                #pragma unroll
                for (int q = 0; q < 4; q++) acc[mt][n8][q] = 0.f;

        #pragma unroll 4
        for (int k0 = 0; k0 < 256; k0 += 16) {
            uint32_t ahi_f[2][4], alo_f[2][4];
            #pragma unroll
            for (int mt = 0; mt < 2; mt++) {
                int r0 = warp_m * 32 + mt * 16 + grp;
                const __nv_bfloat16* pHi = sm + OFF_AHI + r0 * SSTRIDE + k0 + tg * 2;
                const __nv_bfloat16* pLo = sm + OFF_ALO + r0 * SSTRIDE + k0 + tg * 2;
                ahi_f[mt][0] = *(const uint32_t*)(pHi);
                ahi_f[mt][1] = *(const uint32_t*)(pHi + 8 * SSTRIDE);
                ahi_f[mt][2] = *(const uint32_t*)(pHi + 8);
                ahi_f[mt][3] = *(const uint32_t*)(pHi + 8 * SSTRIDE + 8);
                alo_f[mt][0] = *(const uint32_t*)(pLo);
                alo_f[mt][1] = *(const uint32_t*)(pLo + 8 * SSTRIDE);
                alo_f[mt][2] = *(const uint32_t*)(pLo + 8);
                alo_f[mt][3] = *(const uint32_t*)(pLo + 8 * SSTRIDE + 8);
            }
            uint32_t bhi_f[4][2], blo_f[4][2];
            #pragma unroll
            for (int n8 = 0; n8 < 4; n8++) {
                int c0 = warp_n * 32 + n8 * 8 + grp;
                const __nv_bfloat16* pHi = sm + OFF_BHI + c0 * SSTRIDE + k0 + tg * 2;
                const __nv_bfloat16* pLo = sm + OFF_BLO + c0 * SSTRIDE + k0 + tg * 2;
                bhi_f[n8][0] = *(const uint32_t*)(pHi);
                bhi_f[n8][1] = *(const uint32_t*)(pHi + 8);
                blo_f[n8][0] = *(const uint32_t*)(pLo);
                blo_f[n8][1] = *(const uint32_t*)(pLo + 8);
            }
            #pragma unroll
            for (int mt = 0; mt < 2; mt++)
                #pragma unroll
                for (int n8 = 0; n8 < 4; n8++) {
                    MMA_BF16(acc[mt][n8], ahi_f[mt], bhi_f[n8]);
                    MMA_BF16(acc[mt][n8], ahi_f[mt], blo_f[n8]);
                    MMA_BF16(acc[mt][n8], alo_f[mt], bhi_f[n8]);
                }
        }

        // ---- Epilogue: *s + b ------------------------------------------------
        const float* srow = sv + (size_t)eT * 256;
        #pragma unroll
        for (int mt = 0; mt < 2; mt++) {
            int rloc = warp_m * 32 + mt * 16 + grp;
            size_t row0 = (size_t)bm * 128 + rloc;
            #pragma unroll
            for (int n8 = 0; n8 < 4; n8++) {
                int col = bn * 64 + warp_n * 32 + n8 * 8 + tg * 2;
                float s0 = srow[col], s1 = srow[col + 1];
                float b0 = bv[col], b1 = bv[col + 1];
                float2 o0, o1;
                o0.x = acc[mt][n8][0] * s0 + b0;
                o0.y = acc[mt][n8][1] * s1 + b1;
                o1.x = acc[mt][n8][2] * s0 + b0;
                o1.y = acc[mt][n8][3] * s1 + b1;
                *(float2*)(pre + row0 * 256 + col) = o0;
                *(float2*)(pre + (row0 + 8) * 256 + col) = o1;
            }
        }
    }
}

// ---------------------------------------------------------------------------
// Recurrence: round-15 skeleton (skip-wait for local-half warps). For
// intermediate layers, emit split-bf16 y (identical values to gemm's own
// split) instead of fp32; final layer writes fp32 out + hlast.
// ---------------------------------------------------------------------------
__device__ __forceinline__ void mbar_wait_cluster(uint32_t mbar, uint32_t parity)
{
    asm volatile(
        "{\n\t"
        ".reg .pred P1;\n\t"
        "WL_%=:\n\t"
        "mbarrier.try_wait.parity.acquire.cluster.shared::cta.b64 P1, [%0], %1;\n\t"
        "@P1 bra.uni WD_%=;\n\t"
        "bra.uni WL_%=;\n\t"
        "WD_%=:\n\t"
        "}" :: "r"(mbar), "r"(parity) : "memory");
}

__global__ __launch_bounds__(256, 1) __cluster_dims__(2, 1, 1)
void rec_kernel(const float* __restrict__ pre, const float* __restrict__ Whh,
                float* __restrict__ yout,
                __nv_bfloat16* __restrict__ yhi, __nv_bfloat16* __restrict__ ylo,
                float* __restrict__ hlast)
{
    int q = blockIdx.x;
    int c = blockIdx.y;
    int tid = threadIdx.x;
    int tz = tid >> 5;
    int tx = tid & 31;

    float w[4][32];
    #pragma unroll
    for (int a = 0; a < 4; a++) {
        const float* wr = Whh + (size_t)(q * 128 + tx * 4 + a) * Hn + tz * 32;
        #pragma unroll
        for (int j4 = 0; j4 < 8; j4++) {
            float4 v = *(const float4*)(wr + j4 * 4);
            w[a][j4 * 4 + 0] = v.x;
            w[a][j4 * 4 + 1] = v.y;
            w[a][j4 * 4 + 2] = v.z;
            w[a][j4 * 4 + 3] = v.w;
        }
    }

    __shared__ __align__(16) float hbuf[2][4][256];
    __shared__ __align__(16) float part[32][128];
    __shared__ __align__(8) unsigned long long mbar_s;

    for (int i = tid; i < 4 * 256; i += 256) ((float*)hbuf[0])[i] = 0.f;
    if (tid == 0) {
        uint32_t mb = s2u(&mbar_s);
        asm volatile("mbarrier.init.shared.b64 [%0], 256;" :: "r"(mb) : "memory");
    }
    __syncthreads();
    asm volatile("barrier.cluster.arrive.aligned;\n\t"
                 "barrier.cluster.wait.aligned;" ::: "memory");

    int rk = tid & 127;
    int mh = tid >> 7;
    int m0 = mh * 2, m1 = m0 + 1;
    int kg = q * 128 + rk;
    size_t be0 = (size_t)c * 4;

    int early = ((tz >> 2) == q);

    uint32_t my_mbar = s2u(&mbar_s);
    uint32_t peer_mbar;
    asm("mapa.shared::cluster.u32 %0, %1, %2;" : "=r"(peer_mbar)
        : "r"(my_mbar), "r"(q ^ 1));

    uint32_t pa0[2], pa1[2];
    #pragma unroll
    for (int p = 0; p < 2; p++) {
        uint32_t a0 = s2u(&hbuf[p][m0][kg]);
        uint32_t a1 = s2u(&hbuf[p][m1][kg]);
        asm("mapa.shared::cluster.u32 %0, %1, %2;" : "=r"(pa0[p]) : "r"(a0), "r"(q ^ 1));
        asm("mapa.shared::cluster.u32 %0, %1, %2;" : "=r"(pa1[p]) : "r"(a1), "r"(q ^ 1));
    }

    size_t row0 = (be0 + m0) * Ln;
    size_t row1 = (be0 + m1) * Ln;
    const float* pre0 = pre + row0 * Hn + kg;
    const float* pre1 = pre + row1 * Hn + kg;

    int pq = 0;
    unsigned int ph = 0;
    for (int t = 0; t < Ln; t++) {
        float pv0 = pre0[t * Hn];
        float pv1 = pre1[t * Hn];

        if (t > 0) {
            if (!early) mbar_wait_cluster(my_mbar, ph);
            ph ^= 1u;
        }

        float acc[4][4];
        #pragma unroll
        for (int m = 0; m < 4; m++)
            #pragma unroll
            for (int a = 0; a < 4; a++) acc[m][a] = 0.f;

        #pragma unroll
        for (int j4 = 0; j4 < 8; j4++) {
            float4 h0 = *(const float4*)&hbuf[pq][0][tz * 32 + j4 * 4];
            float4 h1 = *(const float4*)&hbuf[pq][1][tz * 32 + j4 * 4];
            float4 h2 = *(const float4*)&hbuf[pq][2][tz * 32 + j4 * 4];
            float4 h3 = *(const float4*)&hbuf[pq][3][tz * 32 + j4 * 4];
            float hv0[4] = {h0.x, h0.y, h0.z, h0.w};
            float hv1[4] = {h1.x, h1.y, h1.z, h1.w};
            float hv2[4] = {h2.x, h2.y, h2.z, h2.w};
            float hv3[4] = {h3.x, h3.y, h3.z, h3.w};
            #pragma unroll
            for (int jj = 0; jj < 4; jj++) {
                int j = j4 * 4 + jj;
                #pragma unroll
                for (int a = 0; a < 4; a++) {
                    acc[0][a] += w[a][j] * hv0[jj];
                    acc[1][a] += w[a][j] * hv1[jj];
                    acc[2][a] += w[a][j] * hv2[jj];
                    acc[3][a] += w[a][j] * hv3[jj];
                }
            }
        }
        #pragma unroll
        for (int m = 0; m < 4; m++)
            *(float4*)&part[tz * 4 + m][tx * 4] =
                make_float4(acc[m][0], acc[m][1], acc[m][2], acc[m][3]);
        __syncthreads();

        float s0 = pv0, s1 = pv1;
        #pragma unroll
        for (int z = 0; z < 8; z++) {
            s0 += part[z * 4 + m0][rk];
            s1 += part[z * 4 + m1][rk];
        }
        float h0n = fast_tanh(s0);
        float h1n = fast_tanh(s1);

        int np = pq ^ 1;
        hbuf[np][m0][kg] = h0n;
        hbuf[np][m1][kg] = h1n;

        if (t < Ln - 1) {
            asm volatile("st.shared::cluster.f32 [%0], %1;" :: "r"(pa0[np]), "f"(h0n));
            asm volatile("st.shared::cluster.f32 [%0], %1;" :: "r"(pa1[np]), "f"(h1n));
            asm volatile("mbarrier.arrive.release.cluster.shared::cluster.b64 _, [%0];"
                         :: "r"(peer_mbar) : "memory");
        }

        if (yhi != nullptr) {
            // intermediate layer: emit split-bf16 y (same values gemm would split)
            __nv_bfloat16 h0h = __float2bfloat16(h0n);
            __nv_bfloat16 h1h = __float2bfloat16(h1n);
            size_t o0 = (row0 + t) * Hn + kg;
            size_t o1 = (row1 + t) * Hn + kg;
            yhi[o0] = h0h;
            yhi[o1] = h1h;
            ylo[o0] = __float2bfloat16(h0n - __bfloat162float(h0h));
            ylo[o1] = __float2bfloat16(h1n - __bfloat162float(h1h));
        } else {
            yout[(row0 + t) * Hn + kg] = h0n;
            yout[(row1 + t) * Hn + kg] = h1n;
            if (hlast != nullptr && t == Ln - 1) {
                hlast[(be0 + m0) * Hn + kg] = h0n;
                hlast[(be0 + m1) * Hn + kg] = h1n;
            }
        }

        __syncthreads();
        pq = np;
    }
}

// ---------------------------------------------------------------------------
// Launch
// ---------------------------------------------------------------------------
extern "C" void kernel_launch(void* const* d_in, const int* in_sizes, int n_in,
                              void* d_out, int out_size)
{
    (void)in_sizes; (void)n_in;
    const float* x     = (const float*)d_in[0];
    const float* convw = (const float*)d_in[1];
    const float* convb = (const float*)d_in[2];
    const float* lng   = (const float*)d_in[3];
    const float* lnb   = (const float*)d_in[4];
    const float* Wih   = (const float*)d_in[5];
    const float* Whh   = (const float*)d_in[6];
    const float* rr    = (const float*)d_in[7];
    const float* ss    = (const float*)d_in[8];
    const float* bb    = (const float*)d_in[9];

    float* out = (float*)d_out;
    size_t h_elems = (size_t)Bn * En * Ln * Hn;
    float* hlast = nullptr;
    if ((size_t)out_size >= h_elems + (size_t)Bn * En * Hn)
        hlast = out + h_elems;

    float *p_ln, *p_pre;
    __nv_bfloat16 *p_uhi, *p_ulo, *p_yhi, *p_ylo, *p_whi, *p_wlo;
    cudaGetSymbolAddress((void**)&p_ln, g_ln);
    cudaGetSymbolAddress((void**)&p_pre, g_pre);
    cudaGetSymbolAddress((void**)&p_uhi, g_uhi);
    cudaGetSymbolAddress((void**)&p_ulo, g_ulo);
    cudaGetSymbolAddress((void**)&p_yhi, g_yhi);
    cudaGetSymbolAddress((void**)&p_ylo, g_ylo);
    cudaGetSymbolAddress((void**)&p_whi, g_whi);
    cudaGetSymbolAddress((void**)&p_wlo, g_wlo);

    static int smem_set = 0;
    if (!smem_set) {
        cudaFuncSetAttribute(gemm4_kernel,
                             cudaFuncAttributeMaxDynamicSharedMemorySize, SM3_BYTES);
        smem_set = 1;
    }

    ln_kernel<<<Bn * Ln, 256>>>(x, lng, lnb, p_ln);
    conv_kernel<<<(Bn * Ln * Dn) / 256, 256>>>(p_ln, convw, convb, p_uhi, p_ulo);

    for (int i = 0; i < NLn; i++) {
        // fold r into W_ih, split to bf16 hi/lo (per layer)
        wprep_kernel<<<(En * Hn * Dn) / 256, 256>>>(
            Wih + (size_t)i * Hn * Dn,
            rr + (size_t)i * En * Dn,
            p_whi, p_wlo);

        const __nv_bfloat16* inhi = (i == 0) ? p_uhi : p_yhi;
        const __nv_bfloat16* inlo = (i == 0) ? p_ulo : p_ylo;
        gemm4_kernel<<<MROWS / 128, 256, SM3_BYTES>>>(
            inhi, inlo, p_whi, p_wlo,
            ss + (size_t)i * En * Hn,
            bb + (size_t)i * Hn,
            p_pre, (i == 0) ? 1 : 0);

        int last = (i == NLn - 1);
        rec_kernel<<<dim3(2, 64), 256>>>(
            p_pre,
            Whh + (size_t)i * Hn * Hn,
            last ? out : (float*)nullptr,
            last ? (__nv_bfloat16*)nullptr : p_yhi,
            last ? (__nv_bfloat16*)nullptr : p_ylo,
            last ? hlast : (float*)nullptr);
    }
}

// round 17
// speedup vs baseline: 1.0029x; 1.0029x over previous
#include <cuda_runtime.h>
#include <cuda_bf16.h>
#include <cstdint>

// Problem constants
#define Bn 32
#define Ln 256
#define Dn 256
#define Hn 256
#define En 8
#define NLn 4
#define Kc 4
#define MROWS (Bn*En*Ln)     // 65536

#define SSTRIDE 264          // bf16 elems per smem row (pad: stride%32banks=4)

__device__ __forceinline__ float fast_tanh(float x)
{
    float y;
    asm("tanh.approx.f32 %0, %1;" : "=f"(y) : "f"(x));
    return y;
}

__device__ __forceinline__ uint32_t s2u(const void* p)
{
    uint32_t a;
    asm("{ .reg .u64 t; cvta.to.shared.u64 t, %1; cvt.u32.u64 %0, t; }"
        : "=r"(a) : "l"(p));
    return a;
}

#define MMA_BF16(c, a, b) \
    asm volatile( \
        "mma.sync.aligned.m16n8k16.row.col.f32.bf16.bf16.f32 " \
        "{%0,%1,%2,%3}, {%4,%5,%6,%7}, {%8,%9}, {%0,%1,%2,%3};" \
        : "+f"((c)[0]), "+f"((c)[1]), "+f"((c)[2]), "+f"((c)[3]) \
        : "r"((a)[0]), "r"((a)[1]), "r"((a)[2]), "r"((a)[3]), \
          "r"((b)[0]), "r"((b)[1]))

// Scratch (device globals - no allocation allowed)
__device__ float g_ln[Bn*Ln*Dn];                              // 8 MB
__device__ float g_pre[(size_t)Bn*En*Ln*Hn];                  // 64 MB
__device__ __nv_bfloat16 g_uhi[Bn*Ln*Dn];                     // 4 MB
__device__ __nv_bfloat16 g_ulo[Bn*Ln*Dn];                     // 4 MB
__device__ __nv_bfloat16 g_yhi[(size_t)Bn*En*Ln*Hn];          // 32 MB
__device__ __nv_bfloat16 g_ylo[(size_t)Bn*En*Ln*Hn];          // 32 MB
__device__ __nv_bfloat16 g_whi[En*Hn*Dn];                     // 1 MB (per layer)
__device__ __nv_bfloat16 g_wlo[En*Hn*Dn];                     // 1 MB

// ---------------------------------------------------------------------------
// LayerNorm
// ---------------------------------------------------------------------------
__global__ void ln_kernel(const float* __restrict__ x, const float* __restrict__ g,
                          const float* __restrict__ bb, float* __restrict__ out)
{
    int token = blockIdx.x;
    int t = threadIdx.x;
    __shared__ float red[8];
    __shared__ float meanv, rstdv;

    float v = x[(size_t)token * Dn + t];

    float s = v;
    #pragma unroll
    for (int o = 16; o > 0; o >>= 1) s += __shfl_xor_sync(0xffffffffu, s, o);
    if ((t & 31) == 0) red[t >> 5] = s;
    __syncthreads();
    if (t == 0) {
        float m = 0.f;
        #pragma unroll
        for (int i = 0; i < 8; i++) m += red[i];
        meanv = m * (1.0f / Dn);
    }
    __syncthreads();

    float d = v - meanv;
    float sq = d * d;
    #pragma unroll
    for (int o = 16; o > 0; o >>= 1) sq += __shfl_xor_sync(0xffffffffu, sq, o);
    if ((t & 31) == 0) red[t >> 5] = sq;
    __syncthreads();
    if (t == 0) {
        float vv = 0.f;
        #pragma unroll
        for (int i = 0; i < 8; i++) vv += red[i];
        rstdv = rsqrtf(vv * (1.0f / Dn) + 1e-5f);
    }
    __syncthreads();

    out[(size_t)token * Dn + t] = d * rstdv * g[t] + bb[t];
}

// ---------------------------------------------------------------------------
// Depthwise causal conv1d (K=4, left pad 3) + bias -> split-bf16 output
// ---------------------------------------------------------------------------
__global__ void conv_kernel(const float* __restrict__ ln, const float* __restrict__ cw,
                            const float* __restrict__ cb,
                            __nv_bfloat16* __restrict__ uhi,
                            __nv_bfloat16* __restrict__ ulo)
{
    int idx = blockIdx.x * 256 + threadIdx.x;
    int d  = idx & 255;
    int l  = (idx >> 8) & 255;
    int b0 = idx >> 16;
    float acc = cb[d];
    #pragma unroll
    for (int j = 0; j < Kc; j++) {
        int ls = l - (Kc - 1) + j;
        if (ls >= 0)
            acc += ln[((size_t)b0 * Ln + ls) * Dn + d] * cw[d * Kc + j];
    }
    __nv_bfloat16 h = __float2bfloat16(acc);
    uhi[idx] = h;
    ulo[idx] = __float2bfloat16(acc - __bfloat162float(h));
}

// ---------------------------------------------------------------------------
// wprep: fold r into W_ih per-ensemble, split to bf16 hi/lo.
// ---------------------------------------------------------------------------
__global__ void wprep_kernel(const float* __restrict__ Wih, const float* __restrict__ rv,
                             __nv_bfloat16* __restrict__ whi,
                             __nv_bfloat16* __restrict__ wlo)
{
    int idx = blockIdx.x * 256 + threadIdx.x;    // En*Hn*Dn = 524288
    int f = idx & 255;
    int h = (idx >> 8) & 255;
    int e = idx >> 16;
    float w = Wih[h * 256 + f] * rv[e * 256 + f];
    __nv_bfloat16 hi = __float2bfloat16(w);
    whi[idx] = hi;
    wlo[idx] = __float2bfloat16(w - __bfloat162float(hi));
}

// ---------------------------------------------------------------------------
// gemm5: gemm4 + register-staged B double-buffer. B tile for bn+1 is fetched
// by LDG during bn's mma phase; at the top of each bn we only STS the already
// -arrived registers (no exposed global latency after bn=0).
// ---------------------------------------------------------------------------
#define OFF_AHI 0
#define OFF_ALO (128*SSTRIDE)
#define OFF_BHI (256*SSTRIDE)
#define OFF_BLO (320*SSTRIDE)
#define SM3_ELEMS (384*SSTRIDE)
#define SM3_BYTES (SM3_ELEMS*2)

__global__ __launch_bounds__(256, 1)
void gemm5_kernel(const __nv_bfloat16* __restrict__ inhi,
                  const __nv_bfloat16* __restrict__ inlo,
                  const __nv_bfloat16* __restrict__ whi,
                  const __nv_bfloat16* __restrict__ wlo,
                  const float* __restrict__ sv,
                  const float* __restrict__ bv, float* __restrict__ pre, int layer0)
{
    extern __shared__ __align__(16) __nv_bfloat16 sm[];
    int tid = threadIdx.x;
    int wid = tid >> 5;
    int lane = tid & 31;
    int bm = blockIdx.x;                 // 512 M-tiles of 128 rows

    int eT = (bm >> 1) & 7;              // ensemble index for this tile

    const __nv_bfloat16* wbh = whi + (size_t)eT * 256 * 256;
    const __nv_bfloat16* wbl = wlo + (size_t)eT * 256 * 256;

    // B-copy mapping (same as gemm4): row = tid>>2 (0..63), kq = (tid&3)*64
    int browi = tid >> 2;
    int bkq   = (tid & 3) * 64;

    // ---- Prefetch B tile bn=0 into registers --------------------------------
    uint4 bh_r[8], bl_r[8];
    {
        const __nv_bfloat16* bh = wbh + (size_t)browi * 256 + bkq;
        const __nv_bfloat16* bl = wbl + (size_t)browi * 256 + bkq;
        #pragma unroll
        for (int g = 0; g < 8; g++) {
            bh_r[g] = *(const uint4*)(bh + g * 8);
            bl_r[g] = *(const uint4*)(bl + g * 8);
        }
    }

    // ---- Copy A tile hi/lo: 128 rows x 256 k (once) -------------------------
    {
        int row = tid >> 1;
        int kh  = (tid & 1) * 128;
        int rowA = bm * 128 + row;
        size_t srcRow = layer0 ? ((size_t)(rowA >> 11) * 256 + (rowA & 255))
                               : (size_t)rowA;
        const __nv_bfloat16* ah = inhi + srcRow * 256 + kh;
        const __nv_bfloat16* al = inlo + srcRow * 256 + kh;
        __nv_bfloat16* dh = sm + OFF_AHI + row * SSTRIDE + kh;
        __nv_bfloat16* dl = sm + OFF_ALO + row * SSTRIDE + kh;
        #pragma unroll
        for (int g = 0; g < 16; g++) {
            *(uint4*)(dh + g * 8) = *(const uint4*)(ah + g * 8);
            *(uint4*)(dl + g * 8) = *(const uint4*)(al + g * 8);
        }
    }

    int warp_m = wid & 3;
    int warp_n = wid >> 2;
    int grp = lane >> 2;
    int tg  = lane & 3;

    for (int bn = 0; bn < 4; bn++) {
        __syncthreads();   // A ready (bn=0) / previous mma reads of B smem done

        // ---- STS the prefetched B tile, then issue LDGs for bn+1 -------------
        {
            __nv_bfloat16* dh = sm + OFF_BHI + browi * SSTRIDE + bkq;
            __nv_bfloat16* dl = sm + OFF_BLO + browi * SSTRIDE + bkq;
            #pragma unroll
            for (int g = 0; g < 8; g++) {
                *(uint4*)(dh + g * 8) = bh_r[g];
                *(uint4*)(dl + g * 8) = bl_r[g];
            }
            if (bn < 3) {
                const __nv_bfloat16* bh = wbh + (size_t)((bn + 1) * 64 + browi) * 256 + bkq;
                const __nv_bfloat16* bl = wbl + (size_t)((bn + 1) * 64 + browi) * 256 + bkq;
                #pragma unroll
                for (int g = 0; g < 8; g++) {
                    bh_r[g] = *(const uint4*)(bh + g * 8);
                    bl_r[g] = *(const uint4*)(bl + g * 8);
                }
            }
        }
        __syncthreads();   // B smem ready

        // ---- Warp mma loop (identical core) ----------------------------------
        float acc[2][4][4];
        #pragma unroll
        for (int mt = 0; mt < 2; mt++)
            #pragma unroll
            for (int n8 = 0; n8 < 4; n8++)
                #pragma unroll
                for (int q = 0; q < 4; q++) acc[mt][n8][q] = 0.f;

        #pragma unroll 4
        for (int k0 = 0; k0 < 256; k0 += 16) {
            uint32_t ahi_f[2][4], alo_f[2][4];
            #pragma unroll
            for (int mt = 0; mt < 2; mt++) {
                int r0 = warp_m * 32 + mt * 16 + grp;
                const __nv_bfloat16* pHi = sm + OFF_AHI + r0 * SSTRIDE + k0 + tg * 2;
                const __nv_bfloat16* pLo = sm + OFF_ALO + r0 * SSTRIDE + k0 + tg * 2;
                ahi_f[mt][0] = *(const uint32_t*)(pHi);
                ahi_f[mt][1] = *(const uint32_t*)(pHi + 8 * SSTRIDE);
                ahi_f[mt][2] = *(const uint32_t*)(pHi + 8);
                ahi_f[mt][3] = *(const uint32_t*)(pHi + 8 * SSTRIDE + 8);
                alo_f[mt][0] = *(const uint32_t*)(pLo);
                alo_f[mt][1] = *(const uint32_t*)(pLo + 8 * SSTRIDE);
                alo_f[mt][2] = *(const uint32_t*)(pLo + 8);
                alo_f[mt][3] = *(const uint32_t*)(pLo + 8 * SSTRIDE + 8);
            }
            uint32_t bhi_f[4][2], blo_f[4][2];
            #pragma unroll
            for (int n8 = 0; n8 < 4; n8++) {
                int c0 = warp_n * 32 + n8 * 8 + grp;
                const __nv_bfloat16* pHi = sm + OFF_BHI + c0 * SSTRIDE + k0 + tg * 2;
                const __nv_bfloat16* pLo = sm + OFF_BLO + c0 * SSTRIDE + k0 + tg * 2;
                bhi_f[n8][0] = *(const uint32_t*)(pHi);
                bhi_f[n8][1] = *(const uint32_t*)(pHi + 8);
                blo_f[n8][0] = *(const uint32_t*)(pLo);
                blo_f[n8][1] = *(const uint32_t*)(pLo + 8);
            }
            #pragma unroll
            for (int mt = 0; mt < 2; mt++)
                #pragma unroll
                for (int n8 = 0; n8 < 4; n8++) {
                    MMA_BF16(acc[mt][n8], ahi_f[mt], bhi_f[n8]);
                    MMA_BF16(acc[mt][n8], ahi_f[mt], blo_f[n8]);
                    MMA_BF16(acc[mt][n8], alo_f[mt], bhi_f[n8]);
                }
        }

        // ---- Epilogue: *s + b ------------------------------------------------
        const float* srow = sv + (size_t)eT * 256;
        #pragma unroll
        for (int mt = 0; mt < 2; mt++) {
            int rloc = warp_m * 32 + mt * 16 + grp;
            size_t row0 = (size_t)bm * 128 + rloc;
            #pragma unroll
            for (int n8 = 0; n8 < 4; n8++) {
                int col = bn * 64 + warp_n * 32 + n8 * 8 + tg * 2;
                float s0 = srow[col], s1 = srow[col + 1];
                float b0 = bv[col], b1 = bv[col + 1];
                float2 o0, o1;
                o0.x = acc[mt][n8][0] * s0 + b0;
                o0.y = acc[mt][n8][1] * s1 + b1;
                o1.x = acc[mt][n8][2] * s0 + b0;
                o1.y = acc[mt][n8][3] * s1 + b1;
                *(float2*)(pre + row0 * 256 + col) = o0;
                *(float2*)(pre + (row0 + 8) * 256 + col) = o1;
            }
        }
    }
}

// ---------------------------------------------------------------------------
// Recurrence: round-15/16 version (skip-wait local-half warps; split-bf16 y
// for intermediate layers, fp32 out + hlast for the last layer).
// ---------------------------------------------------------------------------
__device__ __forceinline__ void mbar_wait_cluster(uint32_t mbar, uint32_t parity)
{
    asm volatile(
        "{\n\t"
        ".reg .pred P1;\n\t"
        "WL_%=:\n\t"
        "mbarrier.try_wait.parity.acquire.cluster.shared::cta.b64 P1, [%0], %1;\n\t"
        "@P1 bra.uni WD_%=;\n\t"
        "bra.uni WL_%=;\n\t"
        "WD_%=:\n\t"
        "}" :: "r"(mbar), "r"(parity) : "memory");
}

__global__ __launch_bounds__(256, 1) __cluster_dims__(2, 1, 1)
void rec_kernel(const float* __restrict__ pre, const float* __restrict__ Whh,
                float* __restrict__ yout,
                __nv_bfloat16* __restrict__ yhi, __nv_bfloat16* __restrict__ ylo,
                float* __restrict__ hlast)
{
    int q = blockIdx.x;
    int c = blockIdx.y;
    int tid = threadIdx.x;
    int tz = tid >> 5;
    int tx = tid & 31;

    float w[4][32];
    #pragma unroll
    for (int a = 0; a < 4; a++) {
        const float* wr = Whh + (size_t)(q * 128 + tx * 4 + a) * Hn + tz * 32;
        #pragma unroll
        for (int j4 = 0; j4 < 8; j4++) {
            float4 v = *(const float4*)(wr + j4 * 4);
            w[a][j4 * 4 + 0] = v.x;
            w[a][j4 * 4 + 1] = v.y;
            w[a][j4 * 4 + 2] = v.z;
            w[a][j4 * 4 + 3] = v.w;
        }
    }

    __shared__ __align__(16) float hbuf[2][4][256];
    __shared__ __align__(16) float part[32][128];
    __shared__ __align__(8) unsigned long long mbar_s;

    for (int i = tid; i < 4 * 256; i += 256) ((float*)hbuf[0])[i] = 0.f;
    if (tid == 0) {
        uint32_t mb = s2u(&mbar_s);
        asm volatile("mbarrier.init.shared.b64 [%0], 256;" :: "r"(mb) : "memory");
    }
    __syncthreads();
    asm volatile("barrier.cluster.arrive.aligned;\n\t"
                 "barrier.cluster.wait.aligned;" ::: "memory");

    int rk = tid & 127;
    int mh = tid >> 7;
    int m0 = mh * 2, m1 = m0 + 1;
    int kg = q * 128 + rk;
    size_t be0 = (size_t)c * 4;

    int early = ((tz >> 2) == q);

    uint32_t my_mbar = s2u(&mbar_s);
    uint32_t peer_mbar;
    asm("mapa.shared::cluster.u32 %0, %1, %2;" : "=r"(peer_mbar)
        : "r"(my_mbar), "r"(q ^ 1));

    uint32_t pa0[2], pa1[2];
    #pragma unroll
    for (int p = 0; p < 2; p++) {
        uint32_t a0 = s2u(&hbuf[p][m0][kg]);
        uint32_t a1 = s2u(&hbuf[p][m1][kg]);
        asm("mapa.shared::cluster.u32 %0, %1, %2;" : "=r"(pa0[p]) : "r"(a0), "r"(q ^ 1));
        asm("mapa.shared::cluster.u32 %0, %1, %2;" : "=r"(pa1[p]) : "r"(a1), "r"(q ^ 1));
    }

    size_t row0 = (be0 + m0) * Ln;
    size_t row1 = (be0 + m1) * Ln;
    const float* pre0 = pre + row0 * Hn + kg;
    const float* pre1 = pre + row1 * Hn + kg;

    int pq = 0;
    unsigned int ph = 0;
    for (int t = 0; t < Ln; t++) {
        float pv0 = pre0[t * Hn];
        float pv1 = pre1[t * Hn];

        if (t > 0) {
            if (!early) mbar_wait_cluster(my_mbar, ph);
            ph ^= 1u;
        }

        float acc[4][4];
        #pragma unroll
        for (int m = 0; m < 4; m++)
            #pragma unroll
            for (int a = 0; a < 4; a++) acc[m][a] = 0.f;

        #pragma unroll
        for (int j4 = 0; j4 < 8; j4++) {
            float4 h0 = *(const float4*)&hbuf[pq][0][tz * 32 + j4 * 4];
            float4 h1 = *(const float4*)&hbuf[pq][1][tz * 32 + j4 * 4];
            float4 h2 = *(const float4*)&hbuf[pq][2][tz * 32 + j4 * 4];
            float4 h3 = *(const float4*)&hbuf[pq][3][tz * 32 + j4 * 4];
            float hv0[4] = {h0.x, h0.y, h0.z, h0.w};
            float hv1[4] = {h1.x, h1.y, h1.z, h1.w};
            float hv2[4] = {h2.x, h2.y, h2.z, h2.w};
            float hv3[4] = {h3.x, h3.y, h3.z, h3.w};
            #pragma unroll
            for (int jj = 0; jj < 4; jj++) {
                int j = j4 * 4 + jj;
                #pragma unroll
                for (int a = 0; a < 4; a++) {
                    acc[0][a] += w[a][j] * hv0[jj];
                    acc[1][a] += w[a][j] * hv1[jj];
                    acc[2][a] += w[a][j] * hv2[jj];
                    acc[3][a] += w[a][j] * hv3[jj];
                }
            }
        }
        #pragma unroll
        for (int m = 0; m < 4; m++)
            *(float4*)&part[tz * 4 + m][tx * 4] =
                make_float4(acc[m][0], acc[m][1], acc[m][2], acc[m][3]);
        __syncthreads();

        float s0 = pv0, s1 = pv1;
        #pragma unroll
        for (int z = 0; z < 8; z++) {
            s0 += part[z * 4 + m0][rk];
            s1 += part[z * 4 + m1][rk];
        }
        float h0n = fast_tanh(s0);
        float h1n = fast_tanh(s1);

        int np = pq ^ 1;
        hbuf[np][m0][kg] = h0n;
        hbuf[np][m1][kg] = h1n;

        if (t < Ln - 1) {
            asm volatile("st.shared::cluster.f32 [%0], %1;" :: "r"(pa0[np]), "f"(h0n));
            asm volatile("st.shared::cluster.f32 [%0], %1;" :: "r"(pa1[np]), "f"(h1n));
            asm volatile("mbarrier.arrive.release.cluster.shared::cluster.b64 _, [%0];"
                         :: "r"(peer_mbar) : "memory");
        }

        if (yhi != nullptr) {
            __nv_bfloat16 h0h = __float2bfloat16(h0n);
            __nv_bfloat16 h1h = __float2bfloat16(h1n);
            size_t o0 = (row0 + t) * Hn + kg;
            size_t o1 = (row1 + t) * Hn + kg;
            yhi[o0] = h0h;
            yhi[o1] = h1h;
            ylo[o0] = __float2bfloat16(h0n - __bfloat162float(h0h));
            ylo[o1] = __float2bfloat16(h1n - __bfloat162float(h1h));
        } else {
            yout[(row0 + t) * Hn + kg] = h0n;
            yout[(row1 + t) * Hn + kg] = h1n;
            if (hlast != nullptr && t == Ln - 1) {
                hlast[(be0 + m0) * Hn + kg] = h0n;
                hlast[(be0 + m1) * Hn + kg] = h1n;
            }
        }

        __syncthreads();
        pq = np;
    }
}

// ---------------------------------------------------------------------------
// Launch
// ---------------------------------------------------------------------------
extern "C" void kernel_launch(void* const* d_in, const int* in_sizes, int n_in,
                              void* d_out, int out_size)
{
    (void)in_sizes; (void)n_in;
    const float* x     = (const float*)d_in[0];
    const float* convw = (const float*)d_in[1];
    const float* convb = (const float*)d_in[2];
    const float* lng   = (const float*)d_in[3];
    const float* lnb   = (const float*)d_in[4];
    const float* Wih   = (const float*)d_in[5];
    const float* Whh   = (const float*)d_in[6];
    const float* rr    = (const float*)d_in[7];
    const float* ss    = (const float*)d_in[8];
    const float* bb    = (const float*)d_in[9];

    float* out = (float*)d_out;
    size_t h_elems = (size_t)Bn * En * Ln * Hn;
    float* hlast = nullptr;
    if ((size_t)out_size >= h_elems + (size_t)Bn * En * Hn)
        hlast = out + h_elems;

    float *p_ln, *p_pre;
    __nv_bfloat16 *p_uhi, *p_ulo, *p_yhi, *p_ylo, *p_whi, *p_wlo;
    cudaGetSymbolAddress((void**)&p_ln, g_ln);
    cudaGetSymbolAddress((void**)&p_pre, g_pre);
    cudaGetSymbolAddress((void**)&p_uhi, g_uhi);
    cudaGetSymbolAddress((void**)&p_ulo, g_ulo);
    cudaGetSymbolAddress((void**)&p_yhi, g_yhi);
    cudaGetSymbolAddress((void**)&p_ylo, g_ylo);
    cudaGetSymbolAddress((void**)&p_whi, g_whi);
    cudaGetSymbolAddress((void**)&p_wlo, g_wlo);

    static int smem_set = 0;
    if (!smem_set) {
        cudaFuncSetAttribute(gemm5_kernel,
                             cudaFuncAttributeMaxDynamicSharedMemorySize, SM3_BYTES);
        smem_set = 1;
    }

    ln_kernel<<<Bn * Ln, 256>>>(x, lng, lnb, p_ln);
    conv_kernel<<<(Bn * Ln * Dn) / 256, 256>>>(p_ln, convw, convb, p_uhi, p_ulo);

    for (int i = 0; i < NLn; i++) {
        wprep_kernel<<<(En * Hn * Dn) / 256, 256>>>(
            Wih + (size_t)i * Hn * Dn,
            rr + (size_t)i * En * Dn,
            p_whi, p_wlo);

        const __nv_bfloat16* inhi = (i == 0) ? p_uhi : p_yhi;
        const __nv_bfloat16* inlo = (i == 0) ? p_ulo : p_ylo;
        gemm5_kernel<<<MROWS / 128, 256, SM3_BYTES>>>(
            inhi, inlo, p_whi, p_wlo,
            ss + (size_t)i * En * Hn,
            bb + (size_t)i * Hn,
            p_pre, (i == 0) ? 1 : 0);

        int last = (i == NLn - 1);
        rec_kernel<<<dim3(2, 64), 256>>>(
            p_pre,
            Whh + (size_t)i * Hn * Hn,
            last ? out : (float*)nullptr,
            last ? (__nv_bfloat16*)nullptr : p_yhi,
            last ? (__nv_bfloat16*)nullptr : p_ylo,
            last ? hlast : (float*)nullptr);
    }
}